// round 6
// baseline (speedup 1.0000x reference)
#include <cuda_runtime.h>
#include <cstdint>

#define B_  4
#define N_  2048
#define C_  1024
#define H_  8
#define D_  128
#define TOK (B_ * N_)            // 8192 rows
#define BH  (B_ * H_)            // 32 batched heads
#define SCALE_ 0.08838834764831845f  // 128^-0.5
#define EPS_ 1e-5f

// ---------------- device scratch (allocation-free) ----------------
__device__ __align__(16) float g_h    [TOK * C_];
__device__ __align__(16) float g_qkv  [TOK * 3 * C_];
__device__ __align__(16) float g_q    [BH * N_ * D_];
__device__ __align__(16) float g_k    [BH * N_ * D_];
__device__ __align__(16) float g_v    [BH * N_ * D_];
__device__ __align__(16) float g_sc   [(size_t)BH * N_ * N_]; // 512 MB scores
__device__ __align__(16) float g_o    [BH * N_ * D_];
__device__ __align__(16) float g_ocat [TOK * C_];
__device__ __align__(16) float g_x1   [TOK * C_];
__device__ __align__(16) float g_m1   [TOK * C_];
__device__ __align__(16) float g_bnscale[C_];
__device__ __align__(16) float g_bnshift[C_];

// ---------------- helpers ----------------
__device__ __forceinline__ float warpSum(float v) {
    #pragma unroll
    for (int o = 16; o > 0; o >>= 1) v += __shfl_xor_sync(0xffffffffu, v, o);
    return v;
}
__device__ __forceinline__ float warpMax(float v) {
    #pragma unroll
    for (int o = 16; o > 0; o >>= 1) v = fmaxf(v, __shfl_xor_sync(0xffffffffu, v, o));
    return v;
}
__device__ __forceinline__ uint32_t f2tf32(float x) {
    uint32_t r;
    asm("cvt.rna.tf32.f32 %0, %1;" : "=r"(r) : "f"(x));
    return r;
}
__device__ __forceinline__ void mma_tf32(float* c, const uint32_t* a, const uint32_t* b) {
    asm volatile(
        "mma.sync.aligned.m16n8k8.row.col.f32.tf32.tf32.f32 "
        "{%0,%1,%2,%3}, {%4,%5,%6,%7}, {%8,%9}, {%0,%1,%2,%3};\n"
        : "+f"(c[0]), "+f"(c[1]), "+f"(c[2]), "+f"(c[3])
        : "r"(a[0]), "r"(a[1]), "r"(a[2]), "r"(a[3]), "r"(b[0]), "r"(b[1]));
}

// ---------------- LayerNorm ----------------
__global__ void __launch_bounds__(256) layernorm_kernel(
    const float* __restrict__ x, const float* __restrict__ g,
    const float* __restrict__ b, float* __restrict__ out)
{
    size_t row = blockIdx.x;
    int tid = threadIdx.x;
    const float4* xr = (const float4*)(x + row * C_);
    float4 v = xr[tid];
    float s  = v.x + v.y + v.z + v.w;
    float sq = v.x*v.x + v.y*v.y + v.z*v.z + v.w*v.w;

    __shared__ float red[2][8];
    float ws = warpSum(s), wq = warpSum(sq);
    int lane = tid & 31, wid = tid >> 5;
    if (lane == 0) { red[0][wid] = ws; red[1][wid] = wq; }
    __syncthreads();
    float tot = 0.f, totq = 0.f;
    #pragma unroll
    for (int i = 0; i < 8; ++i) { tot += red[0][i]; totq += red[1][i]; }
    float mean = tot * (1.f / C_);
    float var  = totq * (1.f / C_) - mean * mean;
    float rstd = rsqrtf(var + EPS_);

    float4 gg = ((const float4*)g)[tid];
    float4 bb = ((const float4*)b)[tid];
    float4 o4;
    o4.x = (v.x - mean) * rstd * gg.x + bb.x;
    o4.y = (v.y - mean) * rstd * gg.y + bb.y;
    o4.z = (v.z - mean) * rstd * gg.z + bb.z;
    o4.w = (v.w - mean) * rstd * gg.w + bb.w;
    ((float4*)(out + row * C_))[tid] = o4;
}

// ---------------- TF32 tensor-core GEMM, 128 threads, 64x64 warp tiles ----------------
// C[m,n] = alpha * sum_k A[m,k] * B(k,n)
// TRANSB=true : B is [N,K] row-major (weight layout);  false: B is [K,N]
// EPI: 0 none; 1 +bias+resid; 2 elu(+bias); 3 elu(+bias)*scale+shift+resid
#define BM 128
#define BN 128
#define BK 16
#define PAD 8   // row stride 136 words == 8 mod 32 -> conflict-free frag reads

template<int EPI, bool TRANSB>
__global__ void __launch_bounds__(128)
gemm_tc(const float* __restrict__ A, const float* __restrict__ Bm,
        float* __restrict__ C, const float* __restrict__ resid,
        const float* __restrict__ bias, const float* __restrict__ scale,
        const float* __restrict__ shift,
        int M, int N, int K,
        long long sA, long long sB, long long sC, float alpha)
{
    __shared__ uint32_t As[2][BK][BM + PAD];
    __shared__ uint32_t Bs[2][BK][BN + PAD];

    int bz = blockIdx.z;
    A  += sA * bz;  Bm += sB * bz;  C  += sC * bz;
    const float* R = resid ? resid + sC * bz : nullptr;

    int tid  = threadIdx.x;
    int lane = tid & 31, warpId = tid >> 5;
    int grp  = lane >> 2, tig = lane & 3;
    int wm   = (warpId & 1) * 64;   // 2 warps along M
    int wn   = (warpId >> 1) * 64;  // 2 warps along N
    int mBase = blockIdx.y * BM;
    int nBase = blockIdx.x * BN;

    int nnK = tid >> 3;             // 0..15 (NN-B k row)
    int nnN = (tid & 7) * 16;       // 0..112 (NN-B n col)

    float acc[4][8][4];
    #pragma unroll
    for (int mi = 0; mi < 4; ++mi)
        #pragma unroll
        for (int ni = 0; ni < 8; ++ni)
            #pragma unroll
            for (int e = 0; e < 4; ++e) acc[mi][ni][e] = 0.f;

    const float* Arow = A + (size_t)(mBase + tid) * K;
    const float* Brow = Bm + (size_t)(nBase + tid) * K;   // TRANSB path

    float4 av[4], bv[4];
    int nk = K / BK;

    // ---- prologue: load + store tile 0 ----
    {
        #pragma unroll
        for (int j = 0; j < 4; ++j) av[j] = *(const float4*)&Arow[4 * j];
        if (TRANSB) {
            #pragma unroll
            for (int j = 0; j < 4; ++j) bv[j] = *(const float4*)&Brow[4 * j];
        } else {
            #pragma unroll
            for (int j = 0; j < 4; ++j)
                bv[j] = *(const float4*)&Bm[(size_t)nnK * N + nBase + nnN + 4 * j];
        }
        #pragma unroll
        for (int j = 0; j < 4; ++j) {
            As[0][4*j+0][tid] = f2tf32(av[j].x);
            As[0][4*j+1][tid] = f2tf32(av[j].y);
            As[0][4*j+2][tid] = f2tf32(av[j].z);
            As[0][4*j+3][tid] = f2tf32(av[j].w);
        }
        if (TRANSB) {
            #pragma unroll
            for (int j = 0; j < 4; ++j) {
                Bs[0][4*j+0][tid] = f2tf32(bv[j].x);
                Bs[0][4*j+1][tid] = f2tf32(bv[j].y);
                Bs[0][4*j+2][tid] = f2tf32(bv[j].z);
                Bs[0][4*j+3][tid] = f2tf32(bv[j].w);
            }
        } else {
            #pragma unroll
            for (int j = 0; j < 4; ++j) {
                uint4 pk;
                pk.x = f2tf32(bv[j].x); pk.y = f2tf32(bv[j].y);
                pk.z = f2tf32(bv[j].z); pk.w = f2tf32(bv[j].w);
                *(uint4*)&Bs[0][nnK][nnN + 4 * j] = pk;
            }
        }
    }

    for (int it = 0; it < nk; ++it) {
        __syncthreads();
        int buf = it & 1;
        bool more = (it + 1 < nk);
        if (more) {
            int k0 = (it + 1) * BK;
            #pragma unroll
            for (int j = 0; j < 4; ++j) av[j] = *(const float4*)&Arow[k0 + 4 * j];
            if (TRANSB) {
                #pragma unroll
                for (int j = 0; j < 4; ++j) bv[j] = *(const float4*)&Brow[k0 + 4 * j];
            } else {
                #pragma unroll
                for (int j = 0; j < 4; ++j)
                    bv[j] = *(const float4*)&Bm[(size_t)(k0 + nnK) * N + nBase + nnN + 4 * j];
            }
        }

        // ---- compute from smem[buf] ----
        #pragma unroll
        for (int kk = 0; kk < BK; kk += 8) {
            uint32_t af[4][4];
            #pragma unroll
            for (int mi = 0; mi < 4; ++mi) {
                int m = wm + mi * 16 + grp;
                af[mi][0] = As[buf][kk + tig    ][m];
                af[mi][1] = As[buf][kk + tig    ][m + 8];
                af[mi][2] = As[buf][kk + tig + 4][m];
                af[mi][3] = As[buf][kk + tig + 4][m + 8];
            }
            uint32_t bf[8][2];
            #pragma unroll
            for (int ni = 0; ni < 8; ++ni) {
                int n = wn + ni * 8 + grp;
                bf[ni][0] = Bs[buf][kk + tig    ][n];
                bf[ni][1] = Bs[buf][kk + tig + 4][n];
            }
            #pragma unroll
            for (int mi = 0; mi < 4; ++mi)
                #pragma unroll
                for (int ni = 0; ni < 8; ++ni)
                    mma_tf32(acc[mi][ni], af[mi], bf[ni]);
        }

        if (more) {
            int nb = buf ^ 1;
            #pragma unroll
            for (int j = 0; j < 4; ++j) {
                As[nb][4*j+0][tid] = f2tf32(av[j].x);
                As[nb][4*j+1][tid] = f2tf32(av[j].y);
                As[nb][4*j+2][tid] = f2tf32(av[j].z);
                As[nb][4*j+3][tid] = f2tf32(av[j].w);
            }
            if (TRANSB) {
                #pragma unroll
                for (int j = 0; j < 4; ++j) {
                    Bs[nb][4*j+0][tid] = f2tf32(bv[j].x);
                    Bs[nb][4*j+1][tid] = f2tf32(bv[j].y);
                    Bs[nb][4*j+2][tid] = f2tf32(bv[j].z);
                    Bs[nb][4*j+3][tid] = f2tf32(bv[j].w);
                }
            } else {
                #pragma unroll
                for (int j = 0; j < 4; ++j) {
                    uint4 pk;
                    pk.x = f2tf32(bv[j].x); pk.y = f2tf32(bv[j].y);
                    pk.z = f2tf32(bv[j].z); pk.w = f2tf32(bv[j].w);
                    *(uint4*)&Bs[nb][nnK][nnN + 4 * j] = pk;
                }
            }
        }
    }

    // ---- epilogue ----
    #pragma unroll
    for (int mi = 0; mi < 4; ++mi) {
        #pragma unroll
        for (int ni = 0; ni < 8; ++ni) {
            int c0 = nBase + wn + ni * 8 + tig * 2;
            #pragma unroll
            for (int p = 0; p < 2; ++p) {
                int r = mBase + wm + mi * 16 + grp + p * 8;
                size_t idx = (size_t)r * N + c0;
                float v0 = acc[mi][ni][p * 2 + 0] * alpha;
                float v1 = acc[mi][ni][p * 2 + 1] * alpha;
                if (EPI == 1) {
                    v0 += bias[c0]     + R[idx];
                    v1 += bias[c0 + 1] + R[idx + 1];
                } else if (EPI == 2) {
                    v0 += bias[c0];     v0 = v0 > 0.f ? v0 : expm1f(v0);
                    v1 += bias[c0 + 1]; v1 = v1 > 0.f ? v1 : expm1f(v1);
                } else if (EPI == 3) {
                    v0 += bias[c0];     v0 = v0 > 0.f ? v0 : expm1f(v0);
                    v1 += bias[c0 + 1]; v1 = v1 > 0.f ? v1 : expm1f(v1);
                    v0 = v0 * scale[c0]     + shift[c0]     + R[idx];
                    v1 = v1 * scale[c0 + 1] + shift[c0 + 1] + R[idx + 1];
                }
                float2 o2 = make_float2(v0, v1);
                *(float2*)&C[idx] = o2;
            }
        }
    }
}

// ---------------- row softmax over 2048 ----------------
__global__ void __launch_bounds__(256) softmax_kernel(float* __restrict__ s)
{
    size_t row = blockIdx.x;
    float* r = s + row * (size_t)N_;
    int tid = threadIdx.x;

    float vals[8];
    float lmax = -3.4e38f;
    #pragma unroll
    for (int i = 0; i < 8; ++i) {
        vals[i] = r[tid + i * 256];
        lmax = fmaxf(lmax, vals[i]);
    }
    __shared__ float red[8];
    float wm = warpMax(lmax);
    int lane = tid & 31, wid = tid >> 5;
    if (lane == 0) red[wid] = wm;
    __syncthreads();
    float gmax = -3.4e38f;
    #pragma unroll
    for (int i = 0; i < 8; ++i) gmax = fmaxf(gmax, red[i]);
    __syncthreads();

    float lsum = 0.f;
    #pragma unroll
    for (int i = 0; i < 8; ++i) {
        vals[i] = expf(vals[i] - gmax);
        lsum += vals[i];
    }
    float ws = warpSum(lsum);
    if (lane == 0) red[wid] = ws;
    __syncthreads();
    float gsum = 0.f;
    #pragma unroll
    for (int i = 0; i < 8; ++i) gsum += red[i];
    float inv = 1.f / gsum;
    #pragma unroll
    for (int i = 0; i < 8; ++i) r[tid + i * 256] = vals[i] * inv;
}

// ---------------- qkv [B,N,3,H,D] -> q,k,v [BH,N,D] ----------------
__global__ void __launch_bounds__(256) split_qkv_kernel(
    const float* __restrict__ qkv, float* __restrict__ q,
    float* __restrict__ k, float* __restrict__ v)
{
    int idx = blockIdx.x * 256 + threadIdx.x;
    int d = idx & (D_ - 1);
    int n = (idx >> 7) & (N_ - 1);
    int h = (idx >> 18) & (H_ - 1);
    int b = idx >> 21;
    size_t src = (size_t)(b * N_ + n) * (3 * C_) + h * D_ + d;
    q[idx] = qkv[src];
    k[idx] = qkv[src + C_];
    v[idx] = qkv[src + 2 * C_];
}

// ---------------- o [BH,N,D] -> [B,N,C] ----------------
__global__ void __launch_bounds__(256) merge_o_kernel(
    const float* __restrict__ o, float* __restrict__ ocat)
{
    int idx = blockIdx.x * 256 + threadIdx.x;
    int d = idx & (D_ - 1);
    int n = (idx >> 7) & (N_ - 1);
    int h = (idx >> 18) & (H_ - 1);
    int b = idx >> 21;
    ocat[(size_t)(b * N_ + n) * C_ + h * D_ + d] = o[idx];
}

// ---------------- BatchNorm fold ----------------
__global__ void bn_prep_kernel(const float* __restrict__ g, const float* __restrict__ b,
                               const float* __restrict__ mean, const float* __restrict__ var,
                               float* __restrict__ sc, float* __restrict__ sh)
{
    int i = blockIdx.x * 256 + threadIdx.x;
    if (i < C_) {
        float s = g[i] * rsqrtf(var[i] + EPS_);
        sc[i] = s;
        sh[i] = b[i] - mean[i] * s;
    }
}

// ---------------- host ----------------
static float* sym(const void* s) {
    void* p = nullptr;
    cudaGetSymbolAddress(&p, s);
    return (float*)p;
}

extern "C" void kernel_launch(void* const* d_in, const int* in_sizes, int n_in,
                              void* d_out, int out_size)
{
    const float* x      = (const float*)d_in[0];
    const float* ln1_g  = (const float*)d_in[1];
    const float* ln1_b  = (const float*)d_in[2];
    const float* w_qkv  = (const float*)d_in[3];
    const float* w_proj = (const float*)d_in[4];
    const float* b_proj = (const float*)d_in[5];
    const float* ln2_g  = (const float*)d_in[6];
    const float* ln2_b  = (const float*)d_in[7];
    const float* w1     = (const float*)d_in[8];
    const float* b1     = (const float*)d_in[9];
    const float* w2     = (const float*)d_in[10];
    const float* b2     = (const float*)d_in[11];
    const float* bn_g   = (const float*)d_in[12];
    const float* bn_b   = (const float*)d_in[13];
    const float* bn_m   = (const float*)d_in[14];
    const float* bn_v   = (const float*)d_in[15];
    float* out = (float*)d_out;

    float* h    = sym(g_h);
    float* qkv  = sym(g_qkv);
    float* q    = sym(g_q);
    float* k    = sym(g_k);
    float* v    = sym(g_v);
    float* sc   = sym(g_sc);
    float* o    = sym(g_o);
    float* ocat = sym(g_ocat);
    float* x1   = sym(g_x1);
    float* m1   = sym(g_m1);
    float* bns  = sym(g_bnscale);
    float* bnh  = sym(g_bnshift);

    const int elemBlocks = (BH * N_ * D_) / 256;

    // 1) LN1
    layernorm_kernel<<<TOK, 256>>>(x, ln1_g, ln1_b, h);

    // 2) qkv = h @ Wqkv^T
    gemm_tc<0, true><<<dim3(3 * C_ / BN, TOK / BM, 1), 128>>>(
        h, w_qkv, qkv, nullptr, nullptr, nullptr, nullptr,
        TOK, 3 * C_, C_, 0, 0, 0, 1.f);

    // 3) split heads
    split_qkv_kernel<<<elemBlocks, 256>>>(qkv, q, k, v);

    // 4) scores = q @ k^T * SCALE
    gemm_tc<0, true><<<dim3(N_ / BN, N_ / BM, BH), 128>>>(
        q, k, sc, nullptr, nullptr, nullptr, nullptr,
        N_, N_, D_, (long long)N_ * D_, (long long)N_ * D_, (long long)N_ * N_, SCALE_);

    // 5) softmax
    softmax_kernel<<<BH * N_, 256>>>(sc);

    // 6) o = P @ V
    gemm_tc<0, false><<<dim3(D_ / BN, N_ / BM, BH), 128>>>(
        sc, v, o, nullptr, nullptr, nullptr, nullptr,
        N_, D_, N_, (long long)N_ * N_, (long long)N_ * D_, (long long)N_ * D_, 1.f);

    // 7) merge heads
    merge_o_kernel<<<elemBlocks, 256>>>(o, ocat);

    // 8) x1 = ocat @ Wproj^T + b_proj + x
    gemm_tc<1, true><<<dim3(C_ / BN, TOK / BM, 1), 128>>>(
        ocat, w_proj, x1, x, b_proj, nullptr, nullptr,
        TOK, C_, C_, 0, 0, 0, 1.f);

    // 9) LN2
    layernorm_kernel<<<TOK, 256>>>(x1, ln2_g, ln2_b, h);

    // 10) m1 = elu(h @ W1^T + b1)
    gemm_tc<2, true><<<dim3(C_ / BN, TOK / BM, 1), 128>>>(
        h, w1, m1, nullptr, b1, nullptr, nullptr,
        TOK, C_, C_, 0, 0, 0, 1.f);

    // 11) BN fold
    bn_prep_kernel<<<4, 256>>>(bn_g, bn_b, bn_m, bn_v, bns, bnh);

    // 12) out = bn(elu(m1 @ W2^T + b2)) + x1
    gemm_tc<3, true><<<dim3(C_ / BN, TOK / BM, 1), 128>>>(
        m1, w2, out, x1, b2, bns, bnh,
        TOK, C_, C_, 0, 0, 0, 1.f);

    (void)in_sizes; (void)n_in; (void)out_size;
}

// round 9
// speedup vs baseline: 1.4162x; 1.4162x over previous
#include <cuda_runtime.h>
#include <cstdint>

#define B_  4
#define N_  2048
#define C_  1024
#define H_  8
#define D_  128
#define TOK (B_ * N_)            // 8192 rows
#define BH  (B_ * H_)            // 32 batched heads
#define SCALE_ 0.08838834764831845f  // 128^-0.5
#define EPS_ 1e-5f

// ---------------- device scratch (allocation-free) ----------------
__device__ __align__(16) float g_h    [TOK * C_];
__device__ __align__(16) float g_qkv  [TOK * 3 * C_];
__device__ __align__(16) float g_q    [BH * N_ * D_];
__device__ __align__(16) float g_k    [BH * N_ * D_];
__device__ __align__(16) float g_vt   [BH * D_ * N_];   // V transposed: [BH, D, N]
__device__ __align__(16) float g_sc   [(size_t)BH * N_ * N_]; // 512 MB scores
__device__ __align__(16) float g_o    [BH * N_ * D_];
__device__ __align__(16) float g_ocat [TOK * C_];
__device__ __align__(16) float g_x1   [TOK * C_];
__device__ __align__(16) float g_m1   [TOK * C_];
__device__ __align__(16) float g_bnscale[C_];
__device__ __align__(16) float g_bnshift[C_];

// ---------------- helpers ----------------
__device__ __forceinline__ float warpSum(float v) {
    #pragma unroll
    for (int o = 16; o > 0; o >>= 1) v += __shfl_xor_sync(0xffffffffu, v, o);
    return v;
}
__device__ __forceinline__ float warpMax(float v) {
    #pragma unroll
    for (int o = 16; o > 0; o >>= 1) v = fmaxf(v, __shfl_xor_sync(0xffffffffu, v, o));
    return v;
}
__device__ __forceinline__ uint32_t f2tf32(float x) {
    uint32_t r;
    asm("cvt.rna.tf32.f32 %0, %1;" : "=r"(r) : "f"(x));
    return r;
}
__device__ __forceinline__ void mma_tf32(float* c, const uint32_t* a, const uint32_t* b) {
    asm volatile(
        "mma.sync.aligned.m16n8k8.row.col.f32.tf32.tf32.f32 "
        "{%0,%1,%2,%3}, {%4,%5,%6,%7}, {%8,%9}, {%0,%1,%2,%3};\n"
        : "+f"(c[0]), "+f"(c[1]), "+f"(c[2]), "+f"(c[3])
        : "r"(a[0]), "r"(a[1]), "r"(a[2]), "r"(a[3]), "r"(b[0]), "r"(b[1]));
}
__device__ __forceinline__ void ldsm4(uint32_t addr, uint32_t& r0, uint32_t& r1,
                                      uint32_t& r2, uint32_t& r3) {
    asm volatile("ldmatrix.sync.aligned.m8n8.x4.shared.b16 {%0,%1,%2,%3}, [%4];"
                 : "=r"(r0), "=r"(r1), "=r"(r2), "=r"(r3) : "r"(addr));
}

// ---------------- LayerNorm ----------------
__global__ void __launch_bounds__(256) layernorm_kernel(
    const float* __restrict__ x, const float* __restrict__ g,
    const float* __restrict__ b, float* __restrict__ out)
{
    size_t row = blockIdx.x;
    int tid = threadIdx.x;
    const float4* xr = (const float4*)(x + row * C_);
    float4 v = xr[tid];
    float s  = v.x + v.y + v.z + v.w;
    float sq = v.x*v.x + v.y*v.y + v.z*v.z + v.w*v.w;

    __shared__ float red[2][8];
    float ws = warpSum(s), wq = warpSum(sq);
    int lane = tid & 31, wid = tid >> 5;
    if (lane == 0) { red[0][wid] = ws; red[1][wid] = wq; }
    __syncthreads();
    float tot = 0.f, totq = 0.f;
    #pragma unroll
    for (int i = 0; i < 8; ++i) { tot += red[0][i]; totq += red[1][i]; }
    float mean = tot * (1.f / C_);
    float var  = totq * (1.f / C_) - mean * mean;
    float rstd = rsqrtf(var + EPS_);

    float4 gg = ((const float4*)g)[tid];
    float4 bb = ((const float4*)b)[tid];
    float4 o4;
    o4.x = (v.x - mean) * rstd * gg.x + bb.x;
    o4.y = (v.y - mean) * rstd * gg.y + bb.y;
    o4.z = (v.z - mean) * rstd * gg.z + bb.z;
    o4.w = (v.w - mean) * rstd * gg.w + bb.w;
    ((float4*)(out + row * C_))[tid] = o4;
}

// ---------------- TF32 TC GEMM, ldmatrix fragments, all-NT ----------------
// C[m,n] = alpha * sum_k A[m,k] * B[n,k]   (both row-major, K contiguous)
// EPI: 0 none; 1 +bias+resid; 2 elu(+bias); 3 elu(+bias)*scale+shift+resid
#define BM 128
#define BN 128
#define BK 16
#define BKS 20   // row stride in words: r*5 mod 8 covers all 16B bank-groups

template<int EPI>
__global__ void __launch_bounds__(256, 2)
gemm_tc(const float* __restrict__ A, const float* __restrict__ Bm,
        float* __restrict__ C, const float* __restrict__ resid,
        const float* __restrict__ bias, const float* __restrict__ scale,
        const float* __restrict__ shift,
        int M, int N, int K,
        long long sA, long long sB, long long sC, float alpha)
{
    __shared__ uint32_t As[2][BM][BKS];
    __shared__ uint32_t Bs[2][BN][BKS];

    int bz = blockIdx.z;
    A  += sA * bz;  Bm += sB * bz;  C  += sC * bz;
    const float* R = resid ? resid + sC * bz : nullptr;

    int tid  = threadIdx.x;
    int lane = tid & 31, warpId = tid >> 5;
    int grp  = lane >> 2, tig = lane & 3;
    int wm   = (warpId & 3) * 32;   // 4 warps along M -> 32 rows each
    int wn   = (warpId >> 2) * 64;  // 2 warps along N -> 64 cols each
    int mBase = blockIdx.y * BM;
    int nBase = blockIdx.x * BN;

    // global loaders: 2 threads per row, each loads 8 floats of A-row and B-row
    int lRow = tid >> 1;
    int lCol = (tid & 1) * 8;
    const float* Arow = A  + (size_t)(mBase + lRow) * K + lCol;
    const float* Brow = Bm + (size_t)(nBase + lRow) * K + lCol;

    // ldmatrix lane addressing
    int t8 = lane >> 3, r8 = lane & 7;
    int aRowF = wm + (t8 & 1) * 8 + r8;        // + mi*16
    int aColF = (t8 >> 1) * 4;                 // + kk
    int bRowF = wn + (t8 >> 1) * 8 + r8;       // + nb*16
    int bColF = (t8 & 1) * 4;                  // + kk
    uint32_t asBase = (uint32_t)__cvta_generic_to_shared(&As[0][0][0]);
    uint32_t bsBase = (uint32_t)__cvta_generic_to_shared(&Bs[0][0][0]);

    float acc[2][8][4];
    #pragma unroll
    for (int mi = 0; mi < 2; ++mi)
        #pragma unroll
        for (int ni = 0; ni < 8; ++ni)
            #pragma unroll
            for (int e = 0; e < 4; ++e) acc[mi][ni][e] = 0.f;

    float4 av0, av1, bv0, bv1;
    int nk = K / BK;

    // ---- prologue ----
    av0 = *(const float4*)(Arow);     av1 = *(const float4*)(Arow + 4);
    bv0 = *(const float4*)(Brow);     bv1 = *(const float4*)(Brow + 4);
    {
        uint4 ua0, ua1, ub0, ub1;
        ua0.x = f2tf32(av0.x); ua0.y = f2tf32(av0.y); ua0.z = f2tf32(av0.z); ua0.w = f2tf32(av0.w);
        ua1.x = f2tf32(av1.x); ua1.y = f2tf32(av1.y); ua1.z = f2tf32(av1.z); ua1.w = f2tf32(av1.w);
        ub0.x = f2tf32(bv0.x); ub0.y = f2tf32(bv0.y); ub0.z = f2tf32(bv0.z); ub0.w = f2tf32(bv0.w);
        ub1.x = f2tf32(bv1.x); ub1.y = f2tf32(bv1.y); ub1.z = f2tf32(bv1.z); ub1.w = f2tf32(bv1.w);
        *(uint4*)&As[0][lRow][lCol]     = ua0;
        *(uint4*)&As[0][lRow][lCol + 4] = ua1;
        *(uint4*)&Bs[0][lRow][lCol]     = ub0;
        *(uint4*)&Bs[0][lRow][lCol + 4] = ub1;
    }

    for (int it = 0; it < nk; ++it) {
        __syncthreads();
        int buf = it & 1;
        bool more = (it + 1 < nk);
        if (more) {
            int k0 = (it + 1) * BK;
            av0 = *(const float4*)(Arow + k0);     av1 = *(const float4*)(Arow + k0 + 4);
            bv0 = *(const float4*)(Brow + k0);     bv1 = *(const float4*)(Brow + k0 + 4);
        }

        uint32_t aOff = asBase + (uint32_t)(buf * BM * BKS) * 4;
        uint32_t bOff = bsBase + (uint32_t)(buf * BN * BKS) * 4;

        #pragma unroll
        for (int kk = 0; kk < BK; kk += 8) {
            uint32_t af[2][4];
            #pragma unroll
            for (int mi = 0; mi < 2; ++mi) {
                uint32_t ad = aOff + (uint32_t)((aRowF + mi * 16) * BKS + aColF + kk) * 4;
                ldsm4(ad, af[mi][0], af[mi][1], af[mi][2], af[mi][3]);
            }
            uint32_t bf[8][2];
            #pragma unroll
            for (int nb = 0; nb < 4; ++nb) {
                uint32_t bd = bOff + (uint32_t)((bRowF + nb * 16) * BKS + bColF + kk) * 4;
                ldsm4(bd, bf[2*nb][0], bf[2*nb][1], bf[2*nb+1][0], bf[2*nb+1][1]);
            }
            #pragma unroll
            for (int mi = 0; mi < 2; ++mi)
                #pragma unroll
                for (int ni = 0; ni < 8; ++ni)
                    mma_tf32(acc[mi][ni], af[mi], bf[ni]);
        }

        if (more) {
            int nb = buf ^ 1;
            uint4 ua0, ua1, ub0, ub1;
            ua0.x = f2tf32(av0.x); ua0.y = f2tf32(av0.y); ua0.z = f2tf32(av0.z); ua0.w = f2tf32(av0.w);
            ua1.x = f2tf32(av1.x); ua1.y = f2tf32(av1.y); ua1.z = f2tf32(av1.z); ua1.w = f2tf32(av1.w);
            ub0.x = f2tf32(bv0.x); ub0.y = f2tf32(bv0.y); ub0.z = f2tf32(bv0.z); ub0.w = f2tf32(bv0.w);
            ub1.x = f2tf32(bv1.x); ub1.y = f2tf32(bv1.y); ub1.z = f2tf32(bv1.z); ub1.w = f2tf32(bv1.w);
            *(uint4*)&As[nb][lRow][lCol]     = ua0;
            *(uint4*)&As[nb][lRow][lCol + 4] = ua1;
            *(uint4*)&Bs[nb][lRow][lCol]     = ub0;
            *(uint4*)&Bs[nb][lRow][lCol + 4] = ub1;
        }
    }

    // ---- epilogue ----
    #pragma unroll
    for (int mi = 0; mi < 2; ++mi) {
        #pragma unroll
        for (int ni = 0; ni < 8; ++ni) {
            int c0 = nBase + wn + ni * 8 + tig * 2;
            #pragma unroll
            for (int p = 0; p < 2; ++p) {
                int r = mBase + wm + mi * 16 + grp + p * 8;
                size_t idx = (size_t)r * N + c0;
                float v0 = acc[mi][ni][p * 2 + 0] * alpha;
                float v1 = acc[mi][ni][p * 2 + 1] * alpha;
                if (EPI == 1) {
                    v0 += bias[c0]     + R[idx];
                    v1 += bias[c0 + 1] + R[idx + 1];
                } else if (EPI == 2) {
                    v0 += bias[c0];     v0 = v0 > 0.f ? v0 : expm1f(v0);
                    v1 += bias[c0 + 1]; v1 = v1 > 0.f ? v1 : expm1f(v1);
                } else if (EPI == 3) {
                    v0 += bias[c0];     v0 = v0 > 0.f ? v0 : expm1f(v0);
                    v1 += bias[c0 + 1]; v1 = v1 > 0.f ? v1 : expm1f(v1);
                    v0 = v0 * scale[c0]     + shift[c0]     + R[idx];
                    v1 = v1 * scale[c0 + 1] + shift[c0 + 1] + R[idx + 1];
                }
                float2 o2 = make_float2(v0, v1);
                *(float2*)&C[idx] = o2;
            }
        }
    }
}

// ---------------- row softmax over 2048 ----------------
__global__ void __launch_bounds__(256) softmax_kernel(float* __restrict__ s)
{
    size_t row = blockIdx.x;
    float* r = s + row * (size_t)N_;
    int tid = threadIdx.x;

    float vals[8];
    float lmax = -3.4e38f;
    #pragma unroll
    for (int i = 0; i < 8; ++i) {
        vals[i] = r[tid + i * 256];
        lmax = fmaxf(lmax, vals[i]);
    }
    __shared__ float red[8];
    float wm = warpMax(lmax);
    int lane = tid & 31, wid = tid >> 5;
    if (lane == 0) red[wid] = wm;
    __syncthreads();
    float gmax = -3.4e38f;
    #pragma unroll
    for (int i = 0; i < 8; ++i) gmax = fmaxf(gmax, red[i]);
    __syncthreads();

    float lsum = 0.f;
    #pragma unroll
    for (int i = 0; i < 8; ++i) {
        vals[i] = expf(vals[i] - gmax);
        lsum += vals[i];
    }
    float ws = warpSum(lsum);
    if (lane == 0) red[wid] = ws;
    __syncthreads();
    float gsum = 0.f;
    #pragma unroll
    for (int i = 0; i < 8; ++i) gsum += red[i];
    float inv = 1.f / gsum;
    #pragma unroll
    for (int i = 0; i < 8; ++i) r[tid + i * 256] = vals[i] * inv;
}

// ---------------- qkv [B,N,3,H,D] -> q,k [BH,N,D] ----------------
__global__ void __launch_bounds__(256) split_qk_kernel(
    const float* __restrict__ qkv, float* __restrict__ q, float* __restrict__ k)
{
    int idx = blockIdx.x * 256 + threadIdx.x;
    int d = idx & (D_ - 1);
    int n = (idx >> 7) & (N_ - 1);
    int h = (idx >> 18) & (H_ - 1);
    int b = idx >> 21;
    size_t src = (size_t)(b * N_ + n) * (3 * C_) + h * D_ + d;
    q[idx] = qkv[src];
    k[idx] = qkv[src + C_];
}

// ---------------- V transpose: qkv -> vt [BH, D, N] (tiled) ----------------
__global__ void __launch_bounds__(256) transpose_v_kernel(
    const float* __restrict__ qkv, float* __restrict__ vt)
{
    __shared__ float t[32][33];
    int bh = blockIdx.z;
    int b = bh >> 3, h = bh & 7;
    int n0 = blockIdx.x * 32, d0 = blockIdx.y * 32;
    int tx = threadIdx.x & 31, ty = threadIdx.x >> 5;   // 32 x 8
    #pragma unroll
    for (int i = 0; i < 4; ++i) {
        int n = n0 + ty + 8 * i;
        t[ty + 8 * i][tx] = qkv[(size_t)(b * N_ + n) * (3 * C_) + 2 * C_ + h * D_ + d0 + tx];
    }
    __syncthreads();
    #pragma unroll
    for (int i = 0; i < 4; ++i) {
        int d = d0 + ty + 8 * i;
        vt[((size_t)bh * D_ + d) * N_ + n0 + tx] = t[tx][ty + 8 * i];
    }
}

// ---------------- o [BH,N,D] -> [B,N,C] ----------------
__global__ void __launch_bounds__(256) merge_o_kernel(
    const float* __restrict__ o, float* __restrict__ ocat)
{
    int idx = blockIdx.x * 256 + threadIdx.x;
    int d = idx & (D_ - 1);
    int n = (idx >> 7) & (N_ - 1);
    int h = (idx >> 18) & (H_ - 1);
    int b = idx >> 21;
    ocat[(size_t)(b * N_ + n) * C_ + h * D_ + d] = o[idx];
}

// ---------------- BatchNorm fold ----------------
__global__ void bn_prep_kernel(const float* __restrict__ g, const float* __restrict__ b,
                               const float* __restrict__ mean, const float* __restrict__ var,
                               float* __restrict__ sc, float* __restrict__ sh)
{
    int i = blockIdx.x * 256 + threadIdx.x;
    if (i < C_) {
        float s = g[i] * rsqrtf(var[i] + EPS_);
        sc[i] = s;
        sh[i] = b[i] - mean[i] * s;
    }
}

// ---------------- host ----------------
static float* sym(const void* s) {
    void* p = nullptr;
    cudaGetSymbolAddress(&p, s);
    return (float*)p;
}

extern "C" void kernel_launch(void* const* d_in, const int* in_sizes, int n_in,
                              void* d_out, int out_size)
{
    const float* x      = (const float*)d_in[0];
    const float* ln1_g  = (const float*)d_in[1];
    const float* ln1_b  = (const float*)d_in[2];
    const float* w_qkv  = (const float*)d_in[3];
    const float* w_proj = (const float*)d_in[4];
    const float* b_proj = (const float*)d_in[5];
    const float* ln2_g  = (const float*)d_in[6];
    const float* ln2_b  = (const float*)d_in[7];
    const float* w1     = (const float*)d_in[8];
    const float* b1     = (const float*)d_in[9];
    const float* w2     = (const float*)d_in[10];
    const float* b2     = (const float*)d_in[11];
    const float* bn_g   = (const float*)d_in[12];
    const float* bn_b   = (const float*)d_in[13];
    const float* bn_m   = (const float*)d_in[14];
    const float* bn_v   = (const float*)d_in[15];
    float* out = (float*)d_out;

    float* h    = sym(g_h);
    float* qkv  = sym(g_qkv);
    float* q    = sym(g_q);
    float* k    = sym(g_k);
    float* vt   = sym(g_vt);
    float* sc   = sym(g_sc);
    float* o    = sym(g_o);
    float* ocat = sym(g_ocat);
    float* x1   = sym(g_x1);
    float* m1   = sym(g_m1);
    float* bns  = sym(g_bnscale);
    float* bnh  = sym(g_bnshift);

    const int elemBlocks = (BH * N_ * D_) / 256;

    // 1) LN1
    layernorm_kernel<<<TOK, 256>>>(x, ln1_g, ln1_b, h);

    // 2) qkv = h @ Wqkv^T
    gemm_tc<0><<<dim3(3 * C_ / BN, TOK / BM, 1), 256>>>(
        h, w_qkv, qkv, nullptr, nullptr, nullptr, nullptr,
        TOK, 3 * C_, C_, 0, 0, 0, 1.f);

    // 3) split heads (q,k) + transpose V
    split_qk_kernel<<<elemBlocks, 256>>>(qkv, q, k);
    transpose_v_kernel<<<dim3(N_ / 32, D_ / 32, BH), 256>>>(qkv, vt);

    // 4) scores = q @ k^T * SCALE
    gemm_tc<0><<<dim3(N_ / BN, N_ / BM, BH), 256>>>(
        q, k, sc, nullptr, nullptr, nullptr, nullptr,
        N_, N_, D_, (long long)N_ * D_, (long long)N_ * D_, (long long)N_ * N_, SCALE_);

    // 5) softmax
    softmax_kernel<<<BH * N_, 256>>>(sc);

    // 6) o = P @ Vt^T  (NT form: Vt rows are K-contiguous)
    gemm_tc<0><<<dim3(D_ / BN, N_ / BM, BH), 256>>>(
        sc, vt, o, nullptr, nullptr, nullptr, nullptr,
        N_, D_, N_, (long long)N_ * N_, (long long)D_ * N_, (long long)N_ * D_, 1.f);

    // 7) merge heads
    merge_o_kernel<<<elemBlocks, 256>>>(o, ocat);

    // 8) x1 = ocat @ Wproj^T + b_proj + x
    gemm_tc<1><<<dim3(C_ / BN, TOK / BM, 1), 256>>>(
        ocat, w_proj, x1, x, b_proj, nullptr, nullptr,
        TOK, C_, C_, 0, 0, 0, 1.f);

    // 9) LN2
    layernorm_kernel<<<TOK, 256>>>(x1, ln2_g, ln2_b, h);

    // 10) m1 = elu(h @ W1^T + b1)
    gemm_tc<2><<<dim3(C_ / BN, TOK / BM, 1), 256>>>(
        h, w1, m1, nullptr, b1, nullptr, nullptr,
        TOK, C_, C_, 0, 0, 0, 1.f);

    // 11) BN fold
    bn_prep_kernel<<<4, 256>>>(bn_g, bn_b, bn_m, bn_v, bns, bnh);

    // 12) out = bn(elu(m1 @ W2^T + b2)) + x1
    gemm_tc<3><<<dim3(C_ / BN, TOK / BM, 1), 256>>>(
        m1, w2, out, x1, b2, bns, bnh,
        TOK, C_, C_, 0, 0, 0, 1.f);

    (void)in_sizes; (void)n_in; (void)out_size;
}